// round 1
// baseline (speedup 1.0000x reference)
#include <cuda_runtime.h>
#include <math.h>

// Problem constants
#define RN   1024          // rois
#define CCH  384           // channels
#define NCLS 21
#define PPOOL 7
#define DFEAT 18816        // 384*7*7
#define HID  1024
#define BETA (1.0f/9.0f)

// ---------------- scratch (device globals; no allocation allowed) ----------------
__device__ float g_X [RN * DFEAT];   // pooled+flattened features  [1024, 18816]
__device__ float g_H1[RN * HID];     // fc6 out
__device__ float g_H2[RN * HID];     // fc7 out
__device__ float g_cls[RN];          // per-roi classification loss terms
__device__ float g_box[RN];          // per-roi box loss terms

// ---------------- ROIAlign (all 4 FPN levels, level-mapped per roi) --------------
__global__ void roi_align_kernel(const float* __restrict__ p2, const float* __restrict__ p3,
                                 const float* __restrict__ p4, const float* __restrict__ p5,
                                 const float* __restrict__ rois, const int* __restrict__ batch_idx)
{
    int r = blockIdx.x;
    __shared__ float slx[14], sly[14];
    __shared__ int   sx0[14], sx1[14], sy0[14], sy1[14];
    __shared__ int   svx[14], svy[14];

    float x1 = rois[r*4+0], y1 = rois[r*4+1], x2 = rois[r*4+2], y2 = rois[r*4+3];
    float area = (x2 - x1) * (y2 - y1);
    float lf = floorf(4.0f + log2f(sqrtf(area) / 224.0f + 1e-6f));
    lf = fminf(fmaxf(lf, 2.0f), 5.0f);
    int lvl = (int)lf - 2;                 // 0..3
    int S = 56 >> lvl;
    float scale = 0.25f / (float)(1 << lvl);
    const float* feat = (lvl == 0) ? p2 : (lvl == 1) ? p3 : (lvl == 2) ? p4 : p5;
    int b = batch_idx[r];
    const float* img0 = feat + (size_t)b * CCH * S * S;

    float x1s = x1 * scale, y1s = y1 * scale;
    float rw = fmaxf(x2 * scale - x1s, 1.0f);
    float rh = fmaxf(y2 * scale - y1s, 1.0f);

    int t = threadIdx.x;
    if (t < 14) {
        float kk = ((float)t + 0.5f) * 0.5f;   // (k+0.5)/SR, SR=2
        float xs = x1s + (rw / 7.0f) * kk;
        svx[t] = (xs >= -1.0f && xs <= (float)S) ? 1 : 0;
        float x = fminf(fmaxf(xs, 0.0f), (float)(S - 1));
        float x0f = floorf(x);
        slx[t] = x - x0f;
        sx0[t] = (int)x0f;
        sx1[t] = min((int)x0f + 1, S - 1);

        float ys = y1s + (rh / 7.0f) * kk;
        svy[t] = (ys >= -1.0f && ys <= (float)S) ? 1 : 0;
        float y = fminf(fmaxf(ys, 0.0f), (float)(S - 1));
        float y0f = floorf(y);
        sly[t] = y - y0f;
        sy0[t] = (int)y0f;
        sy1[t] = min((int)y0f + 1, S - 1);
    }
    __syncthreads();

    float* Xr = g_X + (size_t)r * DFEAT;
    for (int idx = t; idx < DFEAT; idx += blockDim.x) {
        int c  = idx / 49;
        int pp = idx - c * 49;
        int ph = pp / 7, pw = pp - ph * 7;
        const float* img = img0 + (size_t)c * S * S;
        float acc = 0.0f;
        #pragma unroll
        for (int dy = 0; dy < 2; dy++) {
            int iy = 2 * ph + dy;
            if (!svy[iy]) continue;
            float ly = sly[iy], hy = 1.0f - ly;
            int y0 = sy0[iy] * S, y1r = sy1[iy] * S;
            #pragma unroll
            for (int dx = 0; dx < 2; dx++) {
                int ix = 2 * pw + dx;
                if (!svx[ix]) continue;
                float lx = slx[ix], hx = 1.0f - lx;
                int x0 = sx0[ix], x1i = sx1[ix];
                acc += img[y0 + x0]  * (hy * hx) + img[y0 + x1i]  * (hy * lx)
                     + img[y1r + x0] * (ly * hx) + img[y1r + x1i] * (ly * lx);
            }
        }
        Xr[idx] = acc * 0.25f;   // mean over SRxSR=4 samples (invalids count as 0)
    }
}

// ---------------- fp32 GEMM: C = relu(A[MxK] @ B[KxN] + bias) --------------------
// BM=64, BN=128, BK=16, 256 threads, 4x8 per-thread tile.
// M,N divisible by tile; K divisible by 16 (18816 and 1024 both are).
__global__ void sgemm_bias_relu(const float* __restrict__ A, const float* __restrict__ B,
                                const float* __restrict__ bias, float* __restrict__ Cm,
                                int M, int N, int K, int relu)
{
    __shared__ float As[16][64];
    __shared__ float Bs[16][128];
    int tid = threadIdx.x;
    int bm = blockIdx.y * 64;
    int bn = blockIdx.x * 128;

    int arow = tid >> 2;            // 0..63
    int acol = (tid & 3) << 2;      // 0,4,8,12
    int brow = tid >> 5;            // 0..7
    int bcol = (tid & 31) << 2;     // 0..124
    int ty = tid >> 4;              // 0..15 -> rows ty*4..+3
    int tx = tid & 15;              // cols tx*8..+7

    float acc[4][8];
    #pragma unroll
    for (int i = 0; i < 4; i++)
        #pragma unroll
        for (int j = 0; j < 8; j++) acc[i][j] = 0.0f;

    const float* Aptr  = A + (size_t)(bm + arow) * K + acol;
    const float* Bptr0 = B + (size_t)brow * N + bn + bcol;
    const float* Bptr1 = B + (size_t)(brow + 8) * N + bn + bcol;

    for (int k0 = 0; k0 < K; k0 += 16) {
        float4 a  = *(const float4*)(Aptr + k0);
        float4 b0 = *(const float4*)(Bptr0 + (size_t)k0 * N);
        float4 b1 = *(const float4*)(Bptr1 + (size_t)k0 * N);
        As[acol + 0][arow] = a.x;
        As[acol + 1][arow] = a.y;
        As[acol + 2][arow] = a.z;
        As[acol + 3][arow] = a.w;
        *(float4*)&Bs[brow][bcol]     = b0;
        *(float4*)&Bs[brow + 8][bcol] = b1;
        __syncthreads();
        #pragma unroll
        for (int k = 0; k < 16; k++) {
            float4 av  = *(const float4*)&As[k][ty * 4];
            float4 bv0 = *(const float4*)&Bs[k][tx * 8];
            float4 bv1 = *(const float4*)&Bs[k][tx * 8 + 4];
            float ar[4] = {av.x, av.y, av.z, av.w};
            float br[8] = {bv0.x, bv0.y, bv0.z, bv0.w, bv1.x, bv1.y, bv1.z, bv1.w};
            #pragma unroll
            for (int i = 0; i < 4; i++)
                #pragma unroll
                for (int j = 0; j < 8; j++)
                    acc[i][j] = fmaf(ar[i], br[j], acc[i][j]);
        }
        __syncthreads();
    }

    #pragma unroll
    for (int i = 0; i < 4; i++) {
        int row = bm + ty * 4 + i;
        #pragma unroll
        for (int j = 0; j < 8; j++) {
            int col = bn + tx * 8 + j;
            float v = acc[i][j] + bias[col];
            if (relu) v = fmaxf(v, 0.0f);
            Cm[(size_t)row * N + col] = v;
        }
    }
}

// ---------------- head (cls logits + label-slot bbox) + per-roi losses -----------
__global__ void head_loss_kernel(const float* __restrict__ H2,
                                 const float* __restrict__ w_cls, const float* __restrict__ b_cls,
                                 const float* __restrict__ w_bbox, const float* __restrict__ b_bbox,
                                 const int* __restrict__ labels, const float* __restrict__ regt)
{
    int r = blockIdx.x;
    int t = threadIdx.x;          // 128 threads
    __shared__ float xs[HID];
    __shared__ float logits[NCLS];
    __shared__ float selv[4];

    for (int k = t; k < HID; k += 128) xs[k] = H2[(size_t)r * HID + k];
    __syncthreads();

    int label = labels[r];
    int warp = t >> 5, lane = t & 31;

    for (int j = warp; j < NCLS + 4; j += 4) {
        float s = 0.0f;
        if (j < NCLS) {
            for (int k = lane; k < HID; k += 32) s += xs[k] * w_cls[(size_t)k * NCLS + j];
        } else {
            int col = label * 4 + (j - NCLS);
            for (int k = lane; k < HID; k += 32) s += xs[k] * w_bbox[(size_t)k * (NCLS * 4) + col];
        }
        #pragma unroll
        for (int o = 16; o > 0; o >>= 1) s += __shfl_xor_sync(0xffffffffu, s, o);
        if (lane == 0) {
            if (j < NCLS) logits[j] = s + b_cls[j];
            else          selv[j - NCLS] = s + b_bbox[label * 4 + (j - NCLS)];
        }
    }
    __syncthreads();

    if (t == 0) {
        float m = -1e30f;
        #pragma unroll
        for (int j = 0; j < NCLS; j++) m = fmaxf(m, logits[j]);
        float se = 0.0f;
        #pragma unroll
        for (int j = 0; j < NCLS; j++) se += expf(logits[j] - m);
        float lse = logf(se) + m;
        float ce = lse - logits[label];
        float pt = expf(-ce);
        float fw = (1.0f - pt) * (1.0f - pt);       // gamma = 2
        float aw = (label > 0) ? 0.25f : 0.75f;     // alpha weighting
        g_cls[r] = fw * aw * ce;

        float bl = 0.0f;
        #pragma unroll
        for (int i = 0; i < 4; i++) {
            float d = selv[i] - regt[r * 4 + i];
            float ad = fabsf(d);
            bl += (ad < BETA) ? 0.5f * d * d / BETA : ad - 0.5f * BETA;
        }
        g_box[r] = (label > 0) ? bl : 0.0f;
    }
}

// ---------------- deterministic final reduction ----------------------------------
__global__ void reduce_kernel(float* __restrict__ out)
{
    __shared__ float s1[RN];
    __shared__ float s2[RN];
    int t = threadIdx.x;
    s1[t] = g_cls[t];
    s2[t] = g_box[t];
    __syncthreads();
    for (int o = RN / 2; o > 0; o >>= 1) {
        if (t < o) { s1[t] += s1[t + o]; s2[t] += s2[t + o]; }
        __syncthreads();
    }
    if (t == 0) {
        out[0] = s1[0] / (float)RN;
        out[1] = s2[0] / (float)RN;
    }
}

// ---------------- launch ---------------------------------------------------------
extern "C" void kernel_launch(void* const* d_in, const int* in_sizes, int n_in,
                              void* d_out, int out_size)
{
    const float* p2     = (const float*)d_in[0];
    const float* p3     = (const float*)d_in[1];
    const float* p4     = (const float*)d_in[2];
    const float* p5     = (const float*)d_in[3];
    const float* rois   = (const float*)d_in[4];
    const int*   bidx   = (const int*)  d_in[5];
    const int*   labels = (const int*)  d_in[6];
    const float* regt   = (const float*)d_in[7];
    const float* w_fc6  = (const float*)d_in[8];
    const float* b_fc6  = (const float*)d_in[9];
    const float* w_fc7  = (const float*)d_in[10];
    const float* b_fc7  = (const float*)d_in[11];
    const float* w_cls  = (const float*)d_in[12];
    const float* b_cls  = (const float*)d_in[13];
    const float* w_bbox = (const float*)d_in[14];
    const float* b_bbox = (const float*)d_in[15];

    float *Xp, *H1p, *H2p;
    cudaGetSymbolAddress((void**)&Xp,  g_X);
    cudaGetSymbolAddress((void**)&H1p, g_H1);
    cudaGetSymbolAddress((void**)&H2p, g_H2);

    // 1) ROIAlign + flatten -> g_X [1024, 18816]
    roi_align_kernel<<<RN, 256>>>(p2, p3, p4, p5, rois, bidx);

    // 2) fc6: [1024,18816] @ [18816,1024] + b, relu
    dim3 grid6(HID / 128, RN / 64);
    sgemm_bias_relu<<<grid6, 256>>>(Xp, w_fc6, b_fc6, H1p, RN, HID, DFEAT, 1);

    // 3) fc7: [1024,1024] @ [1024,1024] + b, relu
    sgemm_bias_relu<<<grid6, 256>>>(H1p, w_fc7, b_fc7, H2p, RN, HID, HID, 1);

    // 4) cls/bbox head + per-roi focal / smooth-L1 terms
    head_loss_kernel<<<RN, 128>>>(H2p, w_cls, b_cls, w_bbox, b_bbox, labels, regt);

    // 5) deterministic reduction -> out[0..1]
    reduce_kernel<<<1, RN>>>((float*)d_out);
}

// round 3
// speedup vs baseline: 2.8524x; 2.8524x over previous
#include <cuda_runtime.h>
#include <cuda_bf16.h>
#include <math.h>
#include <stdint.h>

// Problem constants
#define RN   1024
#define CCH  384
#define NCLS 21
#define DFEAT 18816        // 384*7*7
#define HID  1024
#define BETA (1.0f/9.0f)

// GEMM tiling
#define BM 128
#define BN 64
#define BK 32
#define ASTRIDE 40                     // padded row stride (elems) -> conflict-free ldmatrix
#define A_ELEMS (BM*ASTRIDE)           // 5120
#define B_ELEMS (BN*ASTRIDE)           // 2560
#define STAGE_ELEMS (2*A_ELEMS + 2*B_ELEMS)   // 15360 elems (Ahi,Alo,Bhi,Blo)
#define GSMEM_BYTES (2*STAGE_ELEMS*2)  // 61440 bytes, double buffered

// ---------------- scratch (device globals; no allocation allowed) ----------------
__device__ __align__(16) __nv_bfloat16 g_Xhi [RN * DFEAT];
__device__ __align__(16) __nv_bfloat16 g_Xlo [RN * DFEAT];
__device__ __align__(16) __nv_bfloat16 g_W6hi[HID * DFEAT];   // [N,K] transposed
__device__ __align__(16) __nv_bfloat16 g_W6lo[HID * DFEAT];
__device__ __align__(16) __nv_bfloat16 g_W7hi[HID * HID];
__device__ __align__(16) __nv_bfloat16 g_W7lo[HID * HID];
__device__ __align__(16) __nv_bfloat16 g_H1hi[RN * HID];
__device__ __align__(16) __nv_bfloat16 g_H1lo[RN * HID];
__device__ float g_H2[RN * HID];
__device__ float g_cls[RN];
__device__ float g_box[RN];

// ---------------- PTX helpers (baseline sm_80+ features only) ---------------------
__device__ __forceinline__ uint32_t smem_u32(const void* p) {
    uint32_t a;
    asm("{ .reg .u64 t; cvta.to.shared.u64 t, %1; cvt.u32.u64 %0, t; }" : "=r"(a) : "l"(p));
    return a;
}
__device__ __forceinline__ void cp16(void* sdst, const void* gsrc) {
    uint32_t d = smem_u32(sdst);
    asm volatile("cp.async.cg.shared.global [%0], [%1], 16;" :: "r"(d), "l"(gsrc) : "memory");
}
__device__ __forceinline__ void cp_commit() {
    asm volatile("cp.async.commit_group;" ::: "memory");
}
template <int N>
__device__ __forceinline__ void cp_wait() {
    asm volatile("cp.async.wait_group %0;" :: "n"(N) : "memory");
}
__device__ __forceinline__ void ldsm4(uint32_t* r, uint32_t addr) {
    asm volatile("ldmatrix.sync.aligned.m8n8.x4.shared.b16 {%0,%1,%2,%3}, [%4];"
                 : "=r"(r[0]), "=r"(r[1]), "=r"(r[2]), "=r"(r[3]) : "r"(addr));
}
__device__ __forceinline__ void mma16816(float* c, const uint32_t* a, const uint32_t* b) {
    asm volatile("mma.sync.aligned.m16n8k16.row.col.f32.bf16.bf16.f32 "
                 "{%0,%1,%2,%3}, {%4,%5,%6,%7}, {%8,%9}, {%0,%1,%2,%3};"
                 : "+f"(c[0]), "+f"(c[1]), "+f"(c[2]), "+f"(c[3])
                 : "r"(a[0]), "r"(a[1]), "r"(a[2]), "r"(a[3]), "r"(b[0]), "r"(b[1]));
}

// ---------------- ROIAlign: writes split-bf16 X -----------------------------------
__global__ void roi_align_kernel(const float* __restrict__ p2, const float* __restrict__ p3,
                                 const float* __restrict__ p4, const float* __restrict__ p5,
                                 const float* __restrict__ rois, const int* __restrict__ batch_idx)
{
    int r = blockIdx.x;
    __shared__ float slx[14], sly[14];
    __shared__ int   sx0[14], sx1[14], sy0[14], sy1[14];
    __shared__ int   svx[14], svy[14];

    float x1 = rois[r*4+0], y1 = rois[r*4+1], x2 = rois[r*4+2], y2 = rois[r*4+3];
    float area = (x2 - x1) * (y2 - y1);
    float lf = floorf(4.0f + log2f(sqrtf(area) / 224.0f + 1e-6f));
    lf = fminf(fmaxf(lf, 2.0f), 5.0f);
    int lvl = (int)lf - 2;
    int S = 56 >> lvl;
    float scale = 0.25f / (float)(1 << lvl);
    const float* feat = (lvl == 0) ? p2 : (lvl == 1) ? p3 : (lvl == 2) ? p4 : p5;
    int b = batch_idx[r];
    const float* img0 = feat + (size_t)b * CCH * S * S;

    float x1s = x1 * scale, y1s = y1 * scale;
    float rw = fmaxf(x2 * scale - x1s, 1.0f);
    float rh = fmaxf(y2 * scale - y1s, 1.0f);

    int t = threadIdx.x;
    if (t < 14) {
        float kk = ((float)t + 0.5f) * 0.5f;
        float xs = x1s + (rw / 7.0f) * kk;
        svx[t] = (xs >= -1.0f && xs <= (float)S) ? 1 : 0;
        float x = fminf(fmaxf(xs, 0.0f), (float)(S - 1));
        float x0f = floorf(x);
        slx[t] = x - x0f;
        sx0[t] = (int)x0f;
        sx1[t] = min((int)x0f + 1, S - 1);

        float ys = y1s + (rh / 7.0f) * kk;
        svy[t] = (ys >= -1.0f && ys <= (float)S) ? 1 : 0;
        float y = fminf(fmaxf(ys, 0.0f), (float)(S - 1));
        float y0f = floorf(y);
        sly[t] = y - y0f;
        sy0[t] = (int)y0f;
        sy1[t] = min((int)y0f + 1, S - 1);
    }
    __syncthreads();

    size_t rbase = (size_t)r * DFEAT;
    for (int idx = t; idx < DFEAT; idx += blockDim.x) {
        int c  = idx / 49;
        int pp = idx - c * 49;
        int ph = pp / 7, pw = pp - ph * 7;
        const float* img = img0 + (size_t)c * S * S;
        float acc = 0.0f;
        #pragma unroll
        for (int dy = 0; dy < 2; dy++) {
            int iy = 2 * ph + dy;
            if (!svy[iy]) continue;
            float ly = sly[iy], hy = 1.0f - ly;
            int y0 = sy0[iy] * S, y1r = sy1[iy] * S;
            #pragma unroll
            for (int dx = 0; dx < 2; dx++) {
                int ix = 2 * pw + dx;
                if (!svx[ix]) continue;
                float lx = slx[ix], hx = 1.0f - lx;
                int x0 = sx0[ix], x1i = sx1[ix];
                acc += img[y0 + x0]  * (hy * hx) + img[y0 + x1i]  * (hy * lx)
                     + img[y1r + x0] * (ly * hx) + img[y1r + x1i] * (ly * lx);
            }
        }
        float v = acc * 0.25f;
        __nv_bfloat16 h = __float2bfloat16(v);
        g_Xhi[rbase + idx] = h;
        g_Xlo[rbase + idx] = __float2bfloat16(v - __bfloat162float(h));
    }
}

// ---------------- transpose + bf16 split: W[K,N] -> Whi/Wlo [N,K] -----------------
__global__ void transpose_split(const float* __restrict__ W,
                                __nv_bfloat16* __restrict__ Thi, __nv_bfloat16* __restrict__ Tlo,
                                int K, int N)
{
    __shared__ float tile[32][33];
    int k0 = blockIdx.x * 32, n0 = blockIdx.y * 32;
    int tx = threadIdx.x, ty = threadIdx.y;
    #pragma unroll
    for (int i = 0; i < 4; i++)
        tile[ty + i*8][tx] = W[(size_t)(k0 + ty + i*8) * N + n0 + tx];
    __syncthreads();
    #pragma unroll
    for (int i = 0; i < 4; i++) {
        int n = n0 + ty + i*8;
        int k = k0 + tx;
        float v = tile[tx][ty + i*8];
        __nv_bfloat16 h = __float2bfloat16(v);
        Thi[(size_t)n * K + k] = h;
        Tlo[(size_t)n * K + k] = __float2bfloat16(v - __bfloat162float(h));
    }
}

// ---------------- 3xBF16 split GEMM on mma.sync (HMMA) ----------------------------
// C[M=1024, N=1024] = relu(A @ B^T + bias); A=[M,K] hi/lo bf16, B=[N,K] hi/lo bf16.
// mode 0: fp32 out to outf; mode 1: split bf16 out to Ohi/Olo. Output N is HID.
__global__ __launch_bounds__(256, 1)
void gemm3(const __nv_bfloat16* __restrict__ Ahi, const __nv_bfloat16* __restrict__ Alo,
           const __nv_bfloat16* __restrict__ Bhi, const __nv_bfloat16* __restrict__ Blo,
           const float* __restrict__ bias,
           float* __restrict__ outf,
           __nv_bfloat16* __restrict__ Ohi, __nv_bfloat16* __restrict__ Olo,
           int K, int mode)
{
    extern __shared__ __nv_bfloat16 sm[];
    int tid = threadIdx.x, wid = tid >> 5, lane = tid & 31;
    int bm = blockIdx.y * BM, bn = blockIdx.x * BN;
    int wm = (wid & 3) * 32;   // warp M offset within tile
    int wn = (wid >> 2) * 32;  // warp N offset within tile

    float acc[2][4][4];
    #pragma unroll
    for (int mt = 0; mt < 2; mt++)
        #pragma unroll
        for (int nt = 0; nt < 4; nt++)
            #pragma unroll
            for (int i = 0; i < 4; i++) acc[mt][nt][i] = 0.0f;

    // precomputed load indices
    int arow0 = tid >> 2, akc = (tid & 3) * 8;   // + pass*64 rows
    int nc = K / BK;

    // prologue: load stage 0
    {
        const int c = 0, s = 0;
        __nv_bfloat16* st = sm + s * STAGE_ELEMS;
        int k0 = c * BK;
        #pragma unroll
        for (int pass = 0; pass < 2; pass++) {
            int row = arow0 + pass * 64;
            size_t g = (size_t)(bm + row) * K + k0 + akc;
            cp16(&st[row * ASTRIDE + akc], &Ahi[g]);
            cp16(&st[A_ELEMS + row * ASTRIDE + akc], &Alo[g]);
        }
        {
            size_t g = (size_t)(bn + arow0) * K + k0 + akc;
            cp16(&st[2 * A_ELEMS + arow0 * ASTRIDE + akc], &Bhi[g]);
            cp16(&st[2 * A_ELEMS + B_ELEMS + arow0 * ASTRIDE + akc], &Blo[g]);
        }
        cp_commit();
    }

    for (int c = 0; c < nc; c++) {
        int s = c & 1;
        if (c + 1 < nc) {
            int s2 = (c + 1) & 1;
            __nv_bfloat16* st = sm + s2 * STAGE_ELEMS;
            int k0 = (c + 1) * BK;
            #pragma unroll
            for (int pass = 0; pass < 2; pass++) {
                int row = arow0 + pass * 64;
                size_t g = (size_t)(bm + row) * K + k0 + akc;
                cp16(&st[row * ASTRIDE + akc], &Ahi[g]);
                cp16(&st[A_ELEMS + row * ASTRIDE + akc], &Alo[g]);
            }
            {
                size_t g = (size_t)(bn + arow0) * K + k0 + akc;
                cp16(&st[2 * A_ELEMS + arow0 * ASTRIDE + akc], &Bhi[g]);
                cp16(&st[2 * A_ELEMS + B_ELEMS + arow0 * ASTRIDE + akc], &Blo[g]);
            }
            cp_commit();
            cp_wait<1>();
        } else {
            cp_wait<0>();
        }
        __syncthreads();

        __nv_bfloat16* st = sm + s * STAGE_ELEMS;
        uint32_t sA = smem_u32(st);
        #pragma unroll
        for (int ks = 0; ks < 2; ks++) {
            int kc = ks * 16;
            uint32_t ah[2][4], al[2][4], bh[4][2], bl[4][2];
            #pragma unroll
            for (int mt = 0; mt < 2; mt++) {
                int row = wm + mt * 16 + (lane & 15);
                int col = kc + ((lane >> 4) << 3);
                uint32_t off = (uint32_t)(row * ASTRIDE + col) * 2;
                ldsm4(ah[mt], sA + off);
                ldsm4(al[mt], sA + A_ELEMS * 2 + off);
            }
            #pragma unroll
            for (int p = 0; p < 2; p++) {
                int rown = wn + p * 16 + ((lane & 16) >> 1) + (lane & 7);
                int col = kc + (lane & 8);
                uint32_t off = (uint32_t)(rown * ASTRIDE + col) * 2;
                uint32_t r4[4];
                ldsm4(r4, sA + 2 * A_ELEMS * 2 + off);
                bh[2*p][0] = r4[0]; bh[2*p][1] = r4[1];
                bh[2*p+1][0] = r4[2]; bh[2*p+1][1] = r4[3];
                ldsm4(r4, sA + (2 * A_ELEMS + B_ELEMS) * 2 + off);
                bl[2*p][0] = r4[0]; bl[2*p][1] = r4[1];
                bl[2*p+1][0] = r4[2]; bl[2*p+1][1] = r4[3];
            }
            #pragma unroll
            for (int mt = 0; mt < 2; mt++)
                #pragma unroll
                for (int nt = 0; nt < 4; nt++) {
                    mma16816(acc[mt][nt], ah[mt], bh[nt]);
                    mma16816(acc[mt][nt], ah[mt], bl[nt]);
                    mma16816(acc[mt][nt], al[mt], bh[nt]);
                }
        }
        __syncthreads();
    }

    // epilogue
    int lrow = lane >> 2, lcol = (lane & 3) * 2;
    #pragma unroll
    for (int mt = 0; mt < 2; mt++) {
        #pragma unroll
        for (int nt = 0; nt < 4; nt++) {
            int col = bn + wn + nt * 8 + lcol;
            #pragma unroll
            for (int half = 0; half < 2; half++) {
                int row = bm + wm + mt * 16 + lrow + half * 8;
                #pragma unroll
                for (int j = 0; j < 2; j++) {
                    float v = acc[mt][nt][half * 2 + j] + bias[col + j];
                    v = fmaxf(v, 0.0f);
                    size_t o = (size_t)row * HID + col + j;
                    if (mode == 0) {
                        outf[o] = v;
                    } else {
                        __nv_bfloat16 h = __float2bfloat16(v);
                        Ohi[o] = h;
                        Olo[o] = __float2bfloat16(v - __bfloat162float(h));
                    }
                }
            }
        }
    }
}

// ---------------- head (cls logits + label-slot bbox) + per-roi losses ------------
__global__ void head_loss_kernel(const float* __restrict__ H2,
                                 const float* __restrict__ w_cls, const float* __restrict__ b_cls,
                                 const float* __restrict__ w_bbox, const float* __restrict__ b_bbox,
                                 const int* __restrict__ labels, const float* __restrict__ regt)
{
    int r = blockIdx.x;
    int t = threadIdx.x;          // 128 threads
    __shared__ float xs[HID];
    __shared__ float logits[NCLS];
    __shared__ float selv[4];

    for (int k = t; k < HID; k += 128) xs[k] = H2[(size_t)r * HID + k];
    __syncthreads();

    int label = labels[r];
    int warp = t >> 5, lane = t & 31;

    for (int j = warp; j < NCLS + 4; j += 4) {
        float s = 0.0f;
        if (j < NCLS) {
            for (int k = lane; k < HID; k += 32) s += xs[k] * w_cls[(size_t)k * NCLS + j];
        } else {
            int col = label * 4 + (j - NCLS);
            for (int k = lane; k < HID; k += 32) s += xs[k] * w_bbox[(size_t)k * (NCLS * 4) + col];
        }
        #pragma unroll
        for (int o = 16; o > 0; o >>= 1) s += __shfl_xor_sync(0xffffffffu, s, o);
        if (lane == 0) {
            if (j < NCLS) logits[j] = s + b_cls[j];
            else          selv[j - NCLS] = s + b_bbox[label * 4 + (j - NCLS)];
        }
    }
    __syncthreads();

    if (t == 0) {
        float m = -1e30f;
        #pragma unroll
        for (int j = 0; j < NCLS; j++) m = fmaxf(m, logits[j]);
        float se = 0.0f;
        #pragma unroll
        for (int j = 0; j < NCLS; j++) se += expf(logits[j] - m);
        float lse = logf(se) + m;
        float ce = lse - logits[label];
        float pt = expf(-ce);
        float fw = (1.0f - pt) * (1.0f - pt);
        float aw = (label > 0) ? 0.25f : 0.75f;
        g_cls[r] = fw * aw * ce;

        float bl = 0.0f;
        #pragma unroll
        for (int i = 0; i < 4; i++) {
            float d = selv[i] - regt[r * 4 + i];
            float ad = fabsf(d);
            bl += (ad < BETA) ? 0.5f * d * d / BETA : ad - 0.5f * BETA;
        }
        g_box[r] = (label > 0) ? bl : 0.0f;
    }
}

// ---------------- deterministic final reduction -----------------------------------
__global__ void reduce_kernel(float* __restrict__ out)
{
    __shared__ float s1[RN];
    __shared__ float s2[RN];
    int t = threadIdx.x;
    s1[t] = g_cls[t];
    s2[t] = g_box[t];
    __syncthreads();
    for (int o = RN / 2; o > 0; o >>= 1) {
        if (t < o) { s1[t] += s1[t + o]; s2[t] += s2[t + o]; }
        __syncthreads();
    }
    if (t == 0) {
        out[0] = s1[0] / (float)RN;
        out[1] = s2[0] / (float)RN;
    }
}

// ---------------- launch ----------------------------------------------------------
extern "C" void kernel_launch(void* const* d_in, const int* in_sizes, int n_in,
                              void* d_out, int out_size)
{
    const float* p2     = (const float*)d_in[0];
    const float* p3     = (const float*)d_in[1];
    const float* p4     = (const float*)d_in[2];
    const float* p5     = (const float*)d_in[3];
    const float* rois   = (const float*)d_in[4];
    const int*   bidx   = (const int*)  d_in[5];
    const int*   labels = (const int*)  d_in[6];
    const float* regt   = (const float*)d_in[7];
    const float* w_fc6  = (const float*)d_in[8];
    const float* b_fc6  = (const float*)d_in[9];
    const float* w_fc7  = (const float*)d_in[10];
    const float* b_fc7  = (const float*)d_in[11];
    const float* w_cls  = (const float*)d_in[12];
    const float* b_cls  = (const float*)d_in[13];
    const float* w_bbox = (const float*)d_in[14];
    const float* b_bbox = (const float*)d_in[15];

    __nv_bfloat16 *Xhi, *Xlo, *W6hi, *W6lo, *W7hi, *W7lo, *H1hi, *H1lo;
    float *H2p;
    cudaGetSymbolAddress((void**)&Xhi,  g_Xhi);
    cudaGetSymbolAddress((void**)&Xlo,  g_Xlo);
    cudaGetSymbolAddress((void**)&W6hi, g_W6hi);
    cudaGetSymbolAddress((void**)&W6lo, g_W6lo);
    cudaGetSymbolAddress((void**)&W7hi, g_W7hi);
    cudaGetSymbolAddress((void**)&W7lo, g_W7lo);
    cudaGetSymbolAddress((void**)&H1hi, g_H1hi);
    cudaGetSymbolAddress((void**)&H1lo, g_H1lo);
    cudaGetSymbolAddress((void**)&H2p,  g_H2);

    cudaFuncSetAttribute(gemm3, cudaFuncAttributeMaxDynamicSharedMemorySize, GSMEM_BYTES);

    // 1) weight transpose + bf16 split
    transpose_split<<<dim3(DFEAT / 32, HID / 32), dim3(32, 8)>>>(w_fc6, W6hi, W6lo, DFEAT, HID);
    transpose_split<<<dim3(HID / 32, HID / 32),   dim3(32, 8)>>>(w_fc7, W7hi, W7lo, HID, HID);

    // 2) ROIAlign + flatten + split -> g_Xhi/g_Xlo [1024, 18816]
    roi_align_kernel<<<RN, 256>>>(p2, p3, p4, p5, rois, bidx);

    // 3) fc6: H1 = relu(X @ W6^T + b), split-bf16 output
    dim3 grid(HID / BN, RN / BM);   // 16 x 8 = 128 CTAs
    gemm3<<<grid, 256, GSMEM_BYTES>>>(Xhi, Xlo, W6hi, W6lo, b_fc6,
                                      nullptr, H1hi, H1lo, DFEAT, 1);

    // 4) fc7: H2 = relu(H1 @ W7^T + b), fp32 output
    gemm3<<<grid, 256, GSMEM_BYTES>>>(H1hi, H1lo, W7hi, W7lo, b_fc7,
                                      H2p, nullptr, nullptr, HID, 0);

    // 5) heads + per-roi losses
    head_loss_kernel<<<RN, 128>>>(H2p, w_cls, b_cls, w_bbox, b_bbox, labels, regt);

    // 6) deterministic reduction -> out[0..1]
    reduce_kernel<<<1, RN>>>((float*)d_out);
}

// round 4
// speedup vs baseline: 3.4014x; 1.1925x over previous
#include <cuda_runtime.h>
#include <cuda_bf16.h>
#include <math.h>
#include <stdint.h>

// Problem constants
#define RN   1024
#define CCH  384
#define NCLS 21
#define DFEAT 18816        // 384*7*7
#define HID  1024
#define BETA (1.0f/9.0f)

// GEMM tiling
#define BM 128
#define BN 64
#define BK 32
#define ASTRIDE 40                     // padded row stride (elems) -> conflict-free ldmatrix
#define A_ELEMS (BM*ASTRIDE)           // 5120
#define B_ELEMS (BN*ASTRIDE)           // 2560
#define STAGE_ELEMS (2*A_ELEMS + 2*B_ELEMS)   // 15360 elems (Ahi,Alo,Bhi,Blo)
#define GSMEM_BYTES (2*STAGE_ELEMS*2)  // 61440 bytes, double buffered
#define NSPLIT 2

// ---------------- scratch (device globals; no allocation allowed) ----------------
__device__ __align__(16) __nv_bfloat16 g_Xhi [RN * DFEAT];
__device__ __align__(16) __nv_bfloat16 g_Xlo [RN * DFEAT];
__device__ __align__(16) __nv_bfloat16 g_W6hi[HID * DFEAT];   // [N,K] transposed
__device__ __align__(16) __nv_bfloat16 g_W6lo[HID * DFEAT];
__device__ __align__(16) __nv_bfloat16 g_W7hi[HID * HID];
__device__ __align__(16) __nv_bfloat16 g_W7lo[HID * HID];
__device__ __align__(16) __nv_bfloat16 g_H1hi[RN * HID];
__device__ __align__(16) __nv_bfloat16 g_H1lo[RN * HID];
__device__ __align__(16) float g_part[NSPLIT * RN * HID];     // split-K partials
__device__ float g_H2[RN * HID];
__device__ float g_cls[RN];
__device__ float g_box[RN];

// ---------------- PTX helpers (baseline sm_80+ features only) ---------------------
__device__ __forceinline__ uint32_t smem_u32(const void* p) {
    uint32_t a;
    asm("{ .reg .u64 t; cvta.to.shared.u64 t, %1; cvt.u32.u64 %0, t; }" : "=r"(a) : "l"(p));
    return a;
}
__device__ __forceinline__ void cp16(void* sdst, const void* gsrc) {
    uint32_t d = smem_u32(sdst);
    asm volatile("cp.async.cg.shared.global [%0], [%1], 16;" :: "r"(d), "l"(gsrc) : "memory");
}
__device__ __forceinline__ void cp_commit() {
    asm volatile("cp.async.commit_group;" ::: "memory");
}
template <int N>
__device__ __forceinline__ void cp_wait() {
    asm volatile("cp.async.wait_group %0;" :: "n"(N) : "memory");
}
__device__ __forceinline__ void ldsm4(uint32_t* r, uint32_t addr) {
    asm volatile("ldmatrix.sync.aligned.m8n8.x4.shared.b16 {%0,%1,%2,%3}, [%4];"
                 : "=r"(r[0]), "=r"(r[1]), "=r"(r[2]), "=r"(r[3]) : "r"(addr));
}
__device__ __forceinline__ void mma16816(float* c, const uint32_t* a, const uint32_t* b) {
    asm volatile("mma.sync.aligned.m16n8k16.row.col.f32.bf16.bf16.f32 "
                 "{%0,%1,%2,%3}, {%4,%5,%6,%7}, {%8,%9}, {%0,%1,%2,%3};"
                 : "+f"(c[0]), "+f"(c[1]), "+f"(c[2]), "+f"(c[3])
                 : "r"(a[0]), "r"(a[1]), "r"(a[2]), "r"(a[3]), "r"(b[0]), "r"(b[1]));
}

// ---------------- ROIAlign: writes split-bf16 X -----------------------------------
__global__ void roi_align_kernel(const float* __restrict__ p2, const float* __restrict__ p3,
                                 const float* __restrict__ p4, const float* __restrict__ p5,
                                 const float* __restrict__ rois, const int* __restrict__ batch_idx)
{
    int r = blockIdx.x;
    __shared__ float slx[14], sly[14];
    __shared__ int   sx0[14], sx1[14], sy0[14], sy1[14];
    __shared__ int   svx[14], svy[14];

    float x1 = rois[r*4+0], y1 = rois[r*4+1], x2 = rois[r*4+2], y2 = rois[r*4+3];
    float area = (x2 - x1) * (y2 - y1);
    float lf = floorf(4.0f + log2f(sqrtf(area) / 224.0f + 1e-6f));
    lf = fminf(fmaxf(lf, 2.0f), 5.0f);
    int lvl = (int)lf - 2;
    int S = 56 >> lvl;
    float scale = 0.25f / (float)(1 << lvl);
    const float* feat = (lvl == 0) ? p2 : (lvl == 1) ? p3 : (lvl == 2) ? p4 : p5;
    int b = batch_idx[r];
    const float* img0 = feat + (size_t)b * CCH * S * S;

    float x1s = x1 * scale, y1s = y1 * scale;
    float rw = fmaxf(x2 * scale - x1s, 1.0f);
    float rh = fmaxf(y2 * scale - y1s, 1.0f);

    int t = threadIdx.x;
    if (t < 14) {
        float kk = ((float)t + 0.5f) * 0.5f;
        float xs = x1s + (rw / 7.0f) * kk;
        svx[t] = (xs >= -1.0f && xs <= (float)S) ? 1 : 0;
        float x = fminf(fmaxf(xs, 0.0f), (float)(S - 1));
        float x0f = floorf(x);
        slx[t] = x - x0f;
        sx0[t] = (int)x0f;
        sx1[t] = min((int)x0f + 1, S - 1);

        float ys = y1s + (rh / 7.0f) * kk;
        svy[t] = (ys >= -1.0f && ys <= (float)S) ? 1 : 0;
        float y = fminf(fmaxf(ys, 0.0f), (float)(S - 1));
        float y0f = floorf(y);
        sly[t] = y - y0f;
        sy0[t] = (int)y0f;
        sy1[t] = min((int)y0f + 1, S - 1);
    }
    __syncthreads();

    size_t rbase = (size_t)r * DFEAT;
    for (int idx = t; idx < DFEAT; idx += blockDim.x) {
        int c  = idx / 49;
        int pp = idx - c * 49;
        int ph = pp / 7, pw = pp - ph * 7;
        const float* img = img0 + (size_t)c * S * S;
        float acc = 0.0f;
        #pragma unroll
        for (int dy = 0; dy < 2; dy++) {
            int iy = 2 * ph + dy;
            if (!svy[iy]) continue;
            float ly = sly[iy], hy = 1.0f - ly;
            int y0 = sy0[iy] * S, y1r = sy1[iy] * S;
            #pragma unroll
            for (int dx = 0; dx < 2; dx++) {
                int ix = 2 * pw + dx;
                if (!svx[ix]) continue;
                float lx = slx[ix], hx = 1.0f - lx;
                int x0 = sx0[ix], x1i = sx1[ix];
                acc += img[y0 + x0]  * (hy * hx) + img[y0 + x1i]  * (hy * lx)
                     + img[y1r + x0] * (ly * hx) + img[y1r + x1i] * (ly * lx);
            }
        }
        float v = acc * 0.25f;
        __nv_bfloat16 h = __float2bfloat16(v);
        g_Xhi[rbase + idx] = h;
        g_Xlo[rbase + idx] = __float2bfloat16(v - __bfloat162float(h));
    }
}

// ---------------- transpose + bf16 split: W[K,N] -> Whi/Wlo [N,K] -----------------
__global__ void transpose_split(const float* __restrict__ W,
                                __nv_bfloat16* __restrict__ Thi, __nv_bfloat16* __restrict__ Tlo,
                                int K, int N)
{
    __shared__ float tile[32][33];
    int k0 = blockIdx.x * 32, n0 = blockIdx.y * 32;
    int tx = threadIdx.x, ty = threadIdx.y;
    #pragma unroll
    for (int i = 0; i < 4; i++)
        tile[ty + i*8][tx] = W[(size_t)(k0 + ty + i*8) * N + n0 + tx];
    __syncthreads();
    #pragma unroll
    for (int i = 0; i < 4; i++) {
        int n = n0 + ty + i*8;
        int k = k0 + tx;
        float v = tile[tx][ty + i*8];
        __nv_bfloat16 h = __float2bfloat16(v);
        Thi[(size_t)n * K + k] = h;
        Tlo[(size_t)n * K + k] = __float2bfloat16(v - __bfloat162float(h));
    }
}

// ---------------- 3xBF16 split GEMM on mma.sync (HMMA), split-K -------------------
// partial[z][M,N] = A[:, z-th K slice] @ B^T; A=[M,K] hi/lo bf16, B=[N,K] hi/lo.
__global__ __launch_bounds__(256, 2)
void gemm3(const __nv_bfloat16* __restrict__ Ahi, const __nv_bfloat16* __restrict__ Alo,
           const __nv_bfloat16* __restrict__ Bhi, const __nv_bfloat16* __restrict__ Blo,
           float* __restrict__ part, int K, int kLen)
{
    extern __shared__ __nv_bfloat16 sm[];
    int tid = threadIdx.x, wid = tid >> 5, lane = tid & 31;
    int bm = blockIdx.y * BM, bn = blockIdx.x * BN;
    int kOff = blockIdx.z * kLen;
    float* pout = part + (size_t)blockIdx.z * RN * HID;
    int wm = (wid & 3) * 32;   // warp M offset within tile
    int wn = (wid >> 2) * 32;  // warp N offset within tile

    float acc[2][4][4];
    #pragma unroll
    for (int mt = 0; mt < 2; mt++)
        #pragma unroll
        for (int nt = 0; nt < 4; nt++)
            #pragma unroll
            for (int i = 0; i < 4; i++) acc[mt][nt][i] = 0.0f;

    int arow0 = tid >> 2, akc = (tid & 3) * 8;
    int nc = kLen / BK;

    // prologue: load stage 0
    {
        __nv_bfloat16* st = sm;
        int k0 = kOff;
        #pragma unroll
        for (int pass = 0; pass < 2; pass++) {
            int row = arow0 + pass * 64;
            size_t g = (size_t)(bm + row) * K + k0 + akc;
            cp16(&st[row * ASTRIDE + akc], &Ahi[g]);
            cp16(&st[A_ELEMS + row * ASTRIDE + akc], &Alo[g]);
        }
        {
            size_t g = (size_t)(bn + arow0) * K + k0 + akc;
            cp16(&st[2 * A_ELEMS + arow0 * ASTRIDE + akc], &Bhi[g]);
            cp16(&st[2 * A_ELEMS + B_ELEMS + arow0 * ASTRIDE + akc], &Blo[g]);
        }
        cp_commit();
    }

    for (int c = 0; c < nc; c++) {
        int s = c & 1;
        if (c + 1 < nc) {
            int s2 = (c + 1) & 1;
            __nv_bfloat16* st = sm + s2 * STAGE_ELEMS;
            int k0 = kOff + (c + 1) * BK;
            #pragma unroll
            for (int pass = 0; pass < 2; pass++) {
                int row = arow0 + pass * 64;
                size_t g = (size_t)(bm + row) * K + k0 + akc;
                cp16(&st[row * ASTRIDE + akc], &Ahi[g]);
                cp16(&st[A_ELEMS + row * ASTRIDE + akc], &Alo[g]);
            }
            {
                size_t g = (size_t)(bn + arow0) * K + k0 + akc;
                cp16(&st[2 * A_ELEMS + arow0 * ASTRIDE + akc], &Bhi[g]);
                cp16(&st[2 * A_ELEMS + B_ELEMS + arow0 * ASTRIDE + akc], &Blo[g]);
            }
            cp_commit();
            cp_wait<1>();
        } else {
            cp_wait<0>();
        }
        __syncthreads();

        __nv_bfloat16* st = sm + s * STAGE_ELEMS;
        uint32_t sA = smem_u32(st);
        #pragma unroll
        for (int ks = 0; ks < 2; ks++) {
            int kc = ks * 16;
            uint32_t ah[2][4], al[2][4], bh[4][2], bl[4][2];
            #pragma unroll
            for (int mt = 0; mt < 2; mt++) {
                int row = wm + mt * 16 + (lane & 15);
                int col = kc + ((lane >> 4) << 3);
                uint32_t off = (uint32_t)(row * ASTRIDE + col) * 2;
                ldsm4(ah[mt], sA + off);
                ldsm4(al[mt], sA + A_ELEMS * 2 + off);
            }
            #pragma unroll
            for (int p = 0; p < 2; p++) {
                int rown = wn + p * 16 + ((lane & 16) >> 1) + (lane & 7);
                int col = kc + (lane & 8);
                uint32_t off = (uint32_t)(rown * ASTRIDE + col) * 2;
                uint32_t r4[4];
                ldsm4(r4, sA + 2 * A_ELEMS * 2 + off);
                bh[2*p][0] = r4[0]; bh[2*p][1] = r4[1];
                bh[2*p+1][0] = r4[2]; bh[2*p+1][1] = r4[3];
                ldsm4(r4, sA + (2 * A_ELEMS + B_ELEMS) * 2 + off);
                bl[2*p][0] = r4[0]; bl[2*p][1] = r4[1];
                bl[2*p+1][0] = r4[2]; bl[2*p+1][1] = r4[3];
            }
            #pragma unroll
            for (int mt = 0; mt < 2; mt++)
                #pragma unroll
                for (int nt = 0; nt < 4; nt++) {
                    mma16816(acc[mt][nt], ah[mt], bh[nt]);
                    mma16816(acc[mt][nt], ah[mt], bl[nt]);
                    mma16816(acc[mt][nt], al[mt], bh[nt]);
                }
        }
        __syncthreads();
    }

    // epilogue: fp32 partial
    int lrow = lane >> 2, lcol = (lane & 3) * 2;
    #pragma unroll
    for (int mt = 0; mt < 2; mt++) {
        #pragma unroll
        for (int nt = 0; nt < 4; nt++) {
            int col = bn + wn + nt * 8 + lcol;
            #pragma unroll
            for (int half = 0; half < 2; half++) {
                int row = bm + wm + mt * 16 + lrow + half * 8;
                float2 v;
                v.x = acc[mt][nt][half * 2 + 0];
                v.y = acc[mt][nt][half * 2 + 1];
                *(float2*)&pout[(size_t)row * HID + col] = v;
            }
        }
    }
}

// ---------------- combine split-K partials + bias + relu --------------------------
// mode 1: write split bf16 (Ohi/Olo); mode 0: write fp32 (outf).
__global__ void combine_kernel(const float* __restrict__ part, const float* __restrict__ bias,
                               float* __restrict__ outf,
                               __nv_bfloat16* __restrict__ Ohi, __nv_bfloat16* __restrict__ Olo,
                               int mode)
{
    int idx = blockIdx.x * blockDim.x + threadIdx.x;   // over RN*HID
    int col = idx & (HID - 1);
    float v = part[idx] + part[RN * HID + idx] + bias[col];
    v = fmaxf(v, 0.0f);
    if (mode == 0) {
        outf[idx] = v;
    } else {
        __nv_bfloat16 h = __float2bfloat16(v);
        Ohi[idx] = h;
        Olo[idx] = __float2bfloat16(v - __bfloat162float(h));
    }
}

// ---------------- head (cls logits + label-slot bbox) + per-roi losses ------------
__global__ void head_loss_kernel(const float* __restrict__ H2,
                                 const float* __restrict__ w_cls, const float* __restrict__ b_cls,
                                 const float* __restrict__ w_bbox, const float* __restrict__ b_bbox,
                                 const int* __restrict__ labels, const float* __restrict__ regt)
{
    int r = blockIdx.x;
    int t = threadIdx.x;          // 128 threads
    __shared__ float xs[HID];
    __shared__ float logits[NCLS];
    __shared__ float selv[4];

    for (int k = t; k < HID; k += 128) xs[k] = H2[(size_t)r * HID + k];
    __syncthreads();

    int label = labels[r];
    int warp = t >> 5, lane = t & 31;

    for (int j = warp; j < NCLS + 4; j += 4) {
        float s = 0.0f;
        if (j < NCLS) {
            for (int k = lane; k < HID; k += 32) s += xs[k] * w_cls[(size_t)k * NCLS + j];
        } else {
            int col = label * 4 + (j - NCLS);
            for (int k = lane; k < HID; k += 32) s += xs[k] * w_bbox[(size_t)k * (NCLS * 4) + col];
        }
        #pragma unroll
        for (int o = 16; o > 0; o >>= 1) s += __shfl_xor_sync(0xffffffffu, s, o);
        if (lane == 0) {
            if (j < NCLS) logits[j] = s + b_cls[j];
            else          selv[j - NCLS] = s + b_bbox[label * 4 + (j - NCLS)];
        }
    }
    __syncthreads();

    if (t == 0) {
        float m = -1e30f;
        #pragma unroll
        for (int j = 0; j < NCLS; j++) m = fmaxf(m, logits[j]);
        float se = 0.0f;
        #pragma unroll
        for (int j = 0; j < NCLS; j++) se += expf(logits[j] - m);
        float lse = logf(se) + m;
        float ce = lse - logits[label];
        float pt = expf(-ce);
        float fw = (1.0f - pt) * (1.0f - pt);
        float aw = (label > 0) ? 0.25f : 0.75f;
        g_cls[r] = fw * aw * ce;

        float bl = 0.0f;
        #pragma unroll
        for (int i = 0; i < 4; i++) {
            float d = selv[i] - regt[r * 4 + i];
            float ad = fabsf(d);
            bl += (ad < BETA) ? 0.5f * d * d / BETA : ad - 0.5f * BETA;
        }
        g_box[r] = (label > 0) ? bl : 0.0f;
    }
}

// ---------------- deterministic final reduction -----------------------------------
__global__ void reduce_kernel(float* __restrict__ out)
{
    __shared__ float s1[RN];
    __shared__ float s2[RN];
    int t = threadIdx.x;
    s1[t] = g_cls[t];
    s2[t] = g_box[t];
    __syncthreads();
    for (int o = RN / 2; o > 0; o >>= 1) {
        if (t < o) { s1[t] += s1[t + o]; s2[t] += s2[t + o]; }
        __syncthreads();
    }
    if (t == 0) {
        out[0] = s1[0] / (float)RN;
        out[1] = s2[0] / (float)RN;
    }
}

// ---------------- launch ----------------------------------------------------------
extern "C" void kernel_launch(void* const* d_in, const int* in_sizes, int n_in,
                              void* d_out, int out_size)
{
    const float* p2     = (const float*)d_in[0];
    const float* p3     = (const float*)d_in[1];
    const float* p4     = (const float*)d_in[2];
    const float* p5     = (const float*)d_in[3];
    const float* rois   = (const float*)d_in[4];
    const int*   bidx   = (const int*)  d_in[5];
    const int*   labels = (const int*)  d_in[6];
    const float* regt   = (const float*)d_in[7];
    const float* w_fc6  = (const float*)d_in[8];
    const float* b_fc6  = (const float*)d_in[9];
    const float* w_fc7  = (const float*)d_in[10];
    const float* b_fc7  = (const float*)d_in[11];
    const float* w_cls  = (const float*)d_in[12];
    const float* b_cls  = (const float*)d_in[13];
    const float* w_bbox = (const float*)d_in[14];
    const float* b_bbox = (const float*)d_in[15];

    __nv_bfloat16 *Xhi, *Xlo, *W6hi, *W6lo, *W7hi, *W7lo, *H1hi, *H1lo;
    float *H2p, *Pp;
    cudaGetSymbolAddress((void**)&Xhi,  g_Xhi);
    cudaGetSymbolAddress((void**)&Xlo,  g_Xlo);
    cudaGetSymbolAddress((void**)&W6hi, g_W6hi);
    cudaGetSymbolAddress((void**)&W6lo, g_W6lo);
    cudaGetSymbolAddress((void**)&W7hi, g_W7hi);
    cudaGetSymbolAddress((void**)&W7lo, g_W7lo);
    cudaGetSymbolAddress((void**)&H1hi, g_H1hi);
    cudaGetSymbolAddress((void**)&H1lo, g_H1lo);
    cudaGetSymbolAddress((void**)&H2p,  g_H2);
    cudaGetSymbolAddress((void**)&Pp,   g_part);

    cudaFuncSetAttribute(gemm3, cudaFuncAttributeMaxDynamicSharedMemorySize, GSMEM_BYTES);

    // 1) weight transpose + bf16 split
    transpose_split<<<dim3(DFEAT / 32, HID / 32), dim3(32, 8)>>>(w_fc6, W6hi, W6lo, DFEAT, HID);
    transpose_split<<<dim3(HID / 32, HID / 32),   dim3(32, 8)>>>(w_fc7, W7hi, W7lo, HID, HID);

    // 2) ROIAlign + flatten + split -> g_Xhi/g_Xlo [1024, 18816]
    roi_align_kernel<<<RN, 512>>>(p2, p3, p4, p5, rois, bidx);

    // 3) fc6 split-K=2: partials, then combine -> H1 split bf16
    dim3 grid(HID / BN, RN / BM, NSPLIT);   // 16 x 8 x 2 = 256 CTAs
    gemm3<<<grid, 256, GSMEM_BYTES>>>(Xhi, Xlo, W6hi, W6lo, Pp, DFEAT, DFEAT / NSPLIT);
    combine_kernel<<<RN * HID / 256, 256>>>(Pp, b_fc6, nullptr, H1hi, H1lo, 1);

    // 4) fc7 split-K=2 -> H2 fp32
    gemm3<<<grid, 256, GSMEM_BYTES>>>(H1hi, H1lo, W7hi, W7lo, Pp, HID, HID / NSPLIT);
    combine_kernel<<<RN * HID / 256, 256>>>(Pp, b_fc7, H2p, nullptr, nullptr, 0);

    // 5) heads + per-roi losses
    head_loss_kernel<<<RN, 128>>>(H2p, w_cls, b_cls, w_bbox, b_bbox, labels, regt);

    // 6) deterministic reduction -> out[0..1]
    reduce_kernel<<<1, RN>>>((float*)d_out);
}

// round 5
// speedup vs baseline: 3.4016x; 1.0000x over previous
#include <cuda_runtime.h>
#include <cuda_bf16.h>
#include <math.h>
#include <stdint.h>

// Problem constants
#define RN   1024
#define CCH  384
#define NCLS 21
#define DFEAT 18816        // 384*7*7
#define HID  1024
#define BETA (1.0f/9.0f)

// GEMM tiling
#define BM 128
#define BN 64
#define BK 32
#define NST 3                          // pipeline stages
#define ASTRIDE 40                     // padded row stride (elems) -> conflict-free ldmatrix
#define A_ELEMS (BM*ASTRIDE)           // 5120
#define B_ELEMS (BN*ASTRIDE)           // 2560
#define STAGE_ELEMS (2*A_ELEMS + 2*B_ELEMS)   // 15360 elems (Ahi,Alo,Bhi,Blo)
#define GSMEM_BYTES (NST*STAGE_ELEMS*2)       // 92160 bytes
#define NSPLIT 2

// ---------------- scratch (device globals; no allocation allowed) ----------------
__device__ __align__(16) __nv_bfloat16 g_Xhi [RN * DFEAT];
__device__ __align__(16) __nv_bfloat16 g_Xlo [RN * DFEAT];
__device__ __align__(16) __nv_bfloat16 g_W6hi[HID * DFEAT];   // [N,K] transposed
__device__ __align__(16) __nv_bfloat16 g_W6lo[HID * DFEAT];
__device__ __align__(16) __nv_bfloat16 g_W7hi[HID * HID];
__device__ __align__(16) __nv_bfloat16 g_W7lo[HID * HID];
__device__ __align__(16) __nv_bfloat16 g_H1hi[RN * HID];
__device__ __align__(16) __nv_bfloat16 g_H1lo[RN * HID];
__device__ __align__(16) float g_part[NSPLIT * RN * HID];     // split-K partials
__device__ float g_H2[RN * HID];
__device__ float g_cls[RN];
__device__ float g_box[RN];

// ---------------- PTX helpers (baseline sm_80+ features only) ---------------------
__device__ __forceinline__ uint32_t smem_u32(const void* p) {
    uint32_t a;
    asm("{ .reg .u64 t; cvta.to.shared.u64 t, %1; cvt.u32.u64 %0, t; }" : "=r"(a) : "l"(p));
    return a;
}
__device__ __forceinline__ void cp16(void* sdst, const void* gsrc) {
    uint32_t d = smem_u32(sdst);
    asm volatile("cp.async.cg.shared.global [%0], [%1], 16;" :: "r"(d), "l"(gsrc) : "memory");
}
__device__ __forceinline__ void cp_commit() {
    asm volatile("cp.async.commit_group;" ::: "memory");
}
template <int N>
__device__ __forceinline__ void cp_wait() {
    asm volatile("cp.async.wait_group %0;" :: "n"(N) : "memory");
}
__device__ __forceinline__ void ldsm4(uint32_t* r, uint32_t addr) {
    asm volatile("ldmatrix.sync.aligned.m8n8.x4.shared.b16 {%0,%1,%2,%3}, [%4];"
                 : "=r"(r[0]), "=r"(r[1]), "=r"(r[2]), "=r"(r[3]) : "r"(addr));
}
__device__ __forceinline__ void mma16816(float* c, const uint32_t* a, const uint32_t* b) {
    asm volatile("mma.sync.aligned.m16n8k16.row.col.f32.bf16.bf16.f32 "
                 "{%0,%1,%2,%3}, {%4,%5,%6,%7}, {%8,%9}, {%0,%1,%2,%3};"
                 : "+f"(c[0]), "+f"(c[1]), "+f"(c[2]), "+f"(c[3])
                 : "r"(a[0]), "r"(a[1]), "r"(a[2]), "r"(a[3]), "r"(b[0]), "r"(b[1]));
}

// ---------------- ROIAlign: writes split-bf16 X -----------------------------------
__global__ void roi_align_kernel(const float* __restrict__ p2, const float* __restrict__ p3,
                                 const float* __restrict__ p4, const float* __restrict__ p5,
                                 const float* __restrict__ rois, const int* __restrict__ batch_idx)
{
    int r = blockIdx.x;
    __shared__ float slx[14], sly[14];
    __shared__ int   sx0[14], sx1[14], sy0[14], sy1[14];
    __shared__ int   svx[14], svy[14];

    float x1 = rois[r*4+0], y1 = rois[r*4+1], x2 = rois[r*4+2], y2 = rois[r*4+3];
    float area = (x2 - x1) * (y2 - y1);
    float lf = floorf(4.0f + log2f(sqrtf(area) / 224.0f + 1e-6f));
    lf = fminf(fmaxf(lf, 2.0f), 5.0f);
    int lvl = (int)lf - 2;
    int S = 56 >> lvl;
    float scale = 0.25f / (float)(1 << lvl);
    const float* feat = (lvl == 0) ? p2 : (lvl == 1) ? p3 : (lvl == 2) ? p4 : p5;
    int b = batch_idx[r];
    const float* img0 = feat + (size_t)b * CCH * S * S;

    float x1s = x1 * scale, y1s = y1 * scale;
    float rw = fmaxf(x2 * scale - x1s, 1.0f);
    float rh = fmaxf(y2 * scale - y1s, 1.0f);

    int t = threadIdx.x;
    if (t < 14) {
        float kk = ((float)t + 0.5f) * 0.5f;
        float xs = x1s + (rw / 7.0f) * kk;
        svx[t] = (xs >= -1.0f && xs <= (float)S) ? 1 : 0;
        float x = fminf(fmaxf(xs, 0.0f), (float)(S - 1));
        float x0f = floorf(x);
        slx[t] = x - x0f;
        sx0[t] = (int)x0f;
        sx1[t] = min((int)x0f + 1, S - 1);

        float ys = y1s + (rh / 7.0f) * kk;
        svy[t] = (ys >= -1.0f && ys <= (float)S) ? 1 : 0;
        float y = fminf(fmaxf(ys, 0.0f), (float)(S - 1));
        float y0f = floorf(y);
        sly[t] = y - y0f;
        sy0[t] = (int)y0f;
        sy1[t] = min((int)y0f + 1, S - 1);
    }
    __syncthreads();

    size_t rbase = (size_t)r * DFEAT;
    for (int idx = t; idx < DFEAT; idx += blockDim.x) {
        int c  = idx / 49;
        int pp = idx - c * 49;
        int ph = pp / 7, pw = pp - ph * 7;
        const float* img = img0 + (size_t)c * S * S;
        float acc = 0.0f;
        #pragma unroll
        for (int dy = 0; dy < 2; dy++) {
            int iy = 2 * ph + dy;
            if (!svy[iy]) continue;
            float ly = sly[iy], hy = 1.0f - ly;
            int y0 = sy0[iy] * S, y1r = sy1[iy] * S;
            #pragma unroll
            for (int dx = 0; dx < 2; dx++) {
                int ix = 2 * pw + dx;
                if (!svx[ix]) continue;
                float lx = slx[ix], hx = 1.0f - lx;
                int x0 = sx0[ix], x1i = sx1[ix];
                acc += img[y0 + x0]  * (hy * hx) + img[y0 + x1i]  * (hy * lx)
                     + img[y1r + x0] * (ly * hx) + img[y1r + x1i] * (ly * lx);
            }
        }
        float v = acc * 0.25f;
        __nv_bfloat16 h = __float2bfloat16(v);
        g_Xhi[rbase + idx] = h;
        g_Xlo[rbase + idx] = __float2bfloat16(v - __bfloat162float(h));
    }
}

// ---------------- transpose + bf16 split: W[K,N] -> Whi/Wlo [N,K] -----------------
__global__ void transpose_split(const float* __restrict__ W,
                                __nv_bfloat16* __restrict__ Thi, __nv_bfloat16* __restrict__ Tlo,
                                int K, int N)
{
    __shared__ float tile[32][33];
    int k0 = blockIdx.x * 32, n0 = blockIdx.y * 32;
    int tx = threadIdx.x, ty = threadIdx.y;
    #pragma unroll
    for (int i = 0; i < 4; i++)
        tile[ty + i*8][tx] = W[(size_t)(k0 + ty + i*8) * N + n0 + tx];
    __syncthreads();
    #pragma unroll
    for (int i = 0; i < 4; i++) {
        int n = n0 + ty + i*8;
        int k = k0 + tx;
        float v = tile[tx][ty + i*8];
        __nv_bfloat16 h = __float2bfloat16(v);
        Thi[(size_t)n * K + k] = h;
        Tlo[(size_t)n * K + k] = __float2bfloat16(v - __bfloat162float(h));
    }
}

// ---------------- 3xBF16 split GEMM on mma.sync (HMMA), split-K, 3-stage ----------
// partial[z][M,N] = A[:, z-th K slice] @ B^T; A=[M,K] hi/lo bf16, B=[N,K] hi/lo.
__global__ __launch_bounds__(256, 2)
void gemm3(const __nv_bfloat16* __restrict__ Ahi, const __nv_bfloat16* __restrict__ Alo,
           const __nv_bfloat16* __restrict__ Bhi, const __nv_bfloat16* __restrict__ Blo,
           float* __restrict__ part, int K, int kLen)
{
    extern __shared__ __nv_bfloat16 sm[];
    int tid = threadIdx.x, wid = tid >> 5, lane = tid & 31;
    int bm = blockIdx.y * BM, bn = blockIdx.x * BN;
    int kOff = blockIdx.z * kLen;
    float* pout = part + (size_t)blockIdx.z * RN * HID;
    int wm = (wid & 3) * 32;   // warp M offset within tile
    int wn = (wid >> 2) * 32;  // warp N offset within tile

    float acc[2][4][4];
    #pragma unroll
    for (int mt = 0; mt < 2; mt++)
        #pragma unroll
        for (int nt = 0; nt < 4; nt++)
            #pragma unroll
            for (int i = 0; i < 4; i++) acc[mt][nt][i] = 0.0f;

    int arow0 = tid >> 2, akc = (tid & 3) * 8;
    int nc = kLen / BK;

    // stage loader
    auto load_stage = [&](int c, int s) {
        __nv_bfloat16* st = sm + s * STAGE_ELEMS;
        int k0 = kOff + c * BK;
        #pragma unroll
        for (int pass = 0; pass < 2; pass++) {
            int row = arow0 + pass * 64;
            size_t g = (size_t)(bm + row) * K + k0 + akc;
            cp16(&st[row * ASTRIDE + akc], &Ahi[g]);
            cp16(&st[A_ELEMS + row * ASTRIDE + akc], &Alo[g]);
        }
        {
            size_t g = (size_t)(bn + arow0) * K + k0 + akc;
            cp16(&st[2 * A_ELEMS + arow0 * ASTRIDE + akc], &Bhi[g]);
            cp16(&st[2 * A_ELEMS + B_ELEMS + arow0 * ASTRIDE + akc], &Blo[g]);
        }
        cp_commit();
    };

    // prologue: stages 0,1
    load_stage(0, 0);
    load_stage(1, 1);

    for (int c = 0; c < nc; c++) {
        if (c + 1 < nc) cp_wait<1>(); else cp_wait<0>();
        __syncthreads();          // publish stage c%NST; protect stage (c+2)%NST
        if (c + 2 < nc) load_stage(c + 2, (c + 2) % NST);

        __nv_bfloat16* st = sm + (c % NST) * STAGE_ELEMS;
        uint32_t sA = smem_u32(st);
        #pragma unroll
        for (int ks = 0; ks < 2; ks++) {
            int kc = ks * 16;
            uint32_t ah[2][4], al[2][4], bh[4][2], bl[4][2];
            #pragma unroll
            for (int mt = 0; mt < 2; mt++) {
                int row = wm + mt * 16 + (lane & 15);
                int col = kc + ((lane >> 4) << 3);
                uint32_t off = (uint32_t)(row * ASTRIDE + col) * 2;
                ldsm4(ah[mt], sA + off);
                ldsm4(al[mt], sA + A_ELEMS * 2 + off);
            }
            #pragma unroll
            for (int p = 0; p < 2; p++) {
                int rown = wn + p * 16 + ((lane & 16) >> 1) + (lane & 7);
                int col = kc + (lane & 8);
                uint32_t off = (uint32_t)(rown * ASTRIDE + col) * 2;
                uint32_t r4[4];
                ldsm4(r4, sA + 2 * A_ELEMS * 2 + off);
                bh[2*p][0] = r4[0]; bh[2*p][1] = r4[1];
                bh[2*p+1][0] = r4[2]; bh[2*p+1][1] = r4[3];
                ldsm4(r4, sA + (2 * A_ELEMS + B_ELEMS) * 2 + off);
                bl[2*p][0] = r4[0]; bl[2*p][1] = r4[1];
                bl[2*p+1][0] = r4[2]; bl[2*p+1][1] = r4[3];
            }
            // term-major ordering: 8 independent mmas between reuses of same acc
            #pragma unroll
            for (int mt = 0; mt < 2; mt++)
                #pragma unroll
                for (int nt = 0; nt < 4; nt++)
                    mma16816(acc[mt][nt], ah[mt], bh[nt]);
            #pragma unroll
            for (int mt = 0; mt < 2; mt++)
                #pragma unroll
                for (int nt = 0; nt < 4; nt++)
                    mma16816(acc[mt][nt], ah[mt], bl[nt]);
            #pragma unroll
            for (int mt = 0; mt < 2; mt++)
                #pragma unroll
                for (int nt = 0; nt < 4; nt++)
                    mma16816(acc[mt][nt], al[mt], bh[nt]);
        }
    }

    // epilogue: fp32 partial
    int lrow = lane >> 2, lcol = (lane & 3) * 2;
    #pragma unroll
    for (int mt = 0; mt < 2; mt++) {
        #pragma unroll
        for (int nt = 0; nt < 4; nt++) {
            int col = bn + wn + nt * 8 + lcol;
            #pragma unroll
            for (int half = 0; half < 2; half++) {
                int row = bm + wm + mt * 16 + lrow + half * 8;
                float2 v;
                v.x = acc[mt][nt][half * 2 + 0];
                v.y = acc[mt][nt][half * 2 + 1];
                *(float2*)&pout[(size_t)row * HID + col] = v;
            }
        }
    }
}

// ---------------- combine split-K partials + bias + relu --------------------------
__global__ void combine_kernel(const float* __restrict__ part, const float* __restrict__ bias,
                               float* __restrict__ outf,
                               __nv_bfloat16* __restrict__ Ohi, __nv_bfloat16* __restrict__ Olo,
                               int mode)
{
    int idx = blockIdx.x * blockDim.x + threadIdx.x;   // over RN*HID
    int col = idx & (HID - 1);
    float v = part[idx] + part[RN * HID + idx] + bias[col];
    v = fmaxf(v, 0.0f);
    if (mode == 0) {
        outf[idx] = v;
    } else {
        __nv_bfloat16 h = __float2bfloat16(v);
        Ohi[idx] = h;
        Olo[idx] = __float2bfloat16(v - __bfloat162float(h));
    }
}

// ---------------- head (cls logits + label-slot bbox) + per-roi losses ------------
__global__ void head_loss_kernel(const float* __restrict__ H2,
                                 const float* __restrict__ w_cls, const float* __restrict__ b_cls,
                                 const float* __restrict__ w_bbox, const float* __restrict__ b_bbox,
                                 const int* __restrict__ labels, const float* __restrict__ regt)
{
    int r = blockIdx.x;
    int t = threadIdx.x;          // 128 threads
    __shared__ float xs[HID];
    __shared__ float logits[NCLS];
    __shared__ float selv[4];

    for (int k = t; k < HID; k += 128) xs[k] = H2[(size_t)r * HID + k];
    __syncthreads();

    int label = labels[r];
    int warp = t >> 5, lane = t & 31;

    for (int j = warp; j < NCLS + 4; j += 4) {
        float s = 0.0f;
        if (j < NCLS) {
            for (int k = lane; k < HID; k += 32) s += xs[k] * w_cls[(size_t)k * NCLS + j];
        } else {
            int col = label * 4 + (j - NCLS);
            for (int k = lane; k < HID; k += 32) s += xs[k] * w_bbox[(size_t)k * (NCLS * 4) + col];
        }
        #pragma unroll
        for (int o = 16; o > 0; o >>= 1) s += __shfl_xor_sync(0xffffffffu, s, o);
        if (lane == 0) {
            if (j < NCLS) logits[j] = s + b_cls[j];
            else          selv[j - NCLS] = s + b_bbox[label * 4 + (j - NCLS)];
        }
    }
    __syncthreads();

    if (t == 0) {
        float m = -1e30f;
        #pragma unroll
        for (int j = 0; j < NCLS; j++) m = fmaxf(m, logits[j]);
        float se = 0.0f;
        #pragma unroll
        for (int j = 0; j < NCLS; j++) se += expf(logits[j] - m);
        float lse = logf(se) + m;
        float ce = lse - logits[label];
        float pt = expf(-ce);
        float fw = (1.0f - pt) * (1.0f - pt);
        float aw = (label > 0) ? 0.25f : 0.75f;
        g_cls[r] = fw * aw * ce;

        float bl = 0.0f;
        #pragma unroll
        for (int i = 0; i < 4; i++) {
            float d = selv[i] - regt[r * 4 + i];
            float ad = fabsf(d);
            bl += (ad < BETA) ? 0.5f * d * d / BETA : ad - 0.5f * BETA;
        }
        g_box[r] = (label > 0) ? bl : 0.0f;
    }
}

// ---------------- deterministic final reduction -----------------------------------
__global__ void reduce_kernel(float* __restrict__ out)
{
    __shared__ float s1[RN];
    __shared__ float s2[RN];
    int t = threadIdx.x;
    s1[t] = g_cls[t];
    s2[t] = g_box[t];
    __syncthreads();
    for (int o = RN / 2; o > 0; o >>= 1) {
        if (t < o) { s1[t] += s1[t + o]; s2[t] += s2[t + o]; }
        __syncthreads();
    }
    if (t == 0) {
        out[0] = s1[0] / (float)RN;
        out[1] = s2[0] / (float)RN;
    }
}

// ---------------- launch ----------------------------------------------------------
extern "C" void kernel_launch(void* const* d_in, const int* in_sizes, int n_in,
                              void* d_out, int out_size)
{
    const float* p2     = (const float*)d_in[0];
    const float* p3     = (const float*)d_in[1];
    const float* p4     = (const float*)d_in[2];
    const float* p5     = (const float*)d_in[3];
    const float* rois   = (const float*)d_in[4];
    const int*   bidx   = (const int*)  d_in[5];
    const int*   labels = (const int*)  d_in[6];
    const float* regt   = (const float*)d_in[7];
    const float* w_fc6  = (const float*)d_in[8];
    const float* b_fc6  = (const float*)d_in[9];
    const float* w_fc7  = (const float*)d_in[10];
    const float* b_fc7  = (const float*)d_in[11];
    const float* w_cls  = (const float*)d_in[12];
    const float* b_cls  = (const float*)d_in[13];
    const float* w_bbox = (const float*)d_in[14];
    const float* b_bbox = (const float*)d_in[15];

    __nv_bfloat16 *Xhi, *Xlo, *W6hi, *W6lo, *W7hi, *W7lo, *H1hi, *H1lo;
    float *H2p, *Pp;
    cudaGetSymbolAddress((void**)&Xhi,  g_Xhi);
    cudaGetSymbolAddress((void**)&Xlo,  g_Xlo);
    cudaGetSymbolAddress((void**)&W6hi, g_W6hi);
    cudaGetSymbolAddress((void**)&W6lo, g_W6lo);
    cudaGetSymbolAddress((void**)&W7hi, g_W7hi);
    cudaGetSymbolAddress((void**)&W7lo, g_W7lo);
    cudaGetSymbolAddress((void**)&H1hi, g_H1hi);
    cudaGetSymbolAddress((void**)&H1lo, g_H1lo);
    cudaGetSymbolAddress((void**)&H2p,  g_H2);
    cudaGetSymbolAddress((void**)&Pp,   g_part);

    cudaFuncSetAttribute(gemm3, cudaFuncAttributeMaxDynamicSharedMemorySize, GSMEM_BYTES);

    // 1) weight transpose + bf16 split
    transpose_split<<<dim3(DFEAT / 32, HID / 32), dim3(32, 8)>>>(w_fc6, W6hi, W6lo, DFEAT, HID);
    transpose_split<<<dim3(HID / 32, HID / 32),   dim3(32, 8)>>>(w_fc7, W7hi, W7lo, HID, HID);

    // 2) ROIAlign + flatten + split -> g_Xhi/g_Xlo [1024, 18816]
    roi_align_kernel<<<RN, 512>>>(p2, p3, p4, p5, rois, bidx);

    // 3) fc6 split-K=2: partials, then combine -> H1 split bf16
    dim3 grid(HID / BN, RN / BM, NSPLIT);   // 16 x 8 x 2 = 256 CTAs
    gemm3<<<grid, 256, GSMEM_BYTES>>>(Xhi, Xlo, W6hi, W6lo, Pp, DFEAT, DFEAT / NSPLIT);
    combine_kernel<<<RN * HID / 256, 256>>>(Pp, b_fc6, nullptr, H1hi, H1lo, 1);

    // 4) fc7 split-K=2 -> H2 fp32
    gemm3<<<grid, 256, GSMEM_BYTES>>>(H1hi, H1lo, W7hi, W7lo, Pp, HID, HID / NSPLIT);
    combine_kernel<<<RN * HID / 256, 256>>>(Pp, b_fc7, H2p, nullptr, nullptr, 0);

    // 5) heads + per-roi losses
    head_loss_kernel<<<RN, 128>>>(H2p, w_cls, b_cls, w_bbox, b_bbox, labels, regt);

    // 6) deterministic reduction -> out[0..1]
    reduce_kernel<<<1, RN>>>((float*)d_out);
}

// round 6
// speedup vs baseline: 5.7329x; 1.6854x over previous
#include <cuda_runtime.h>
#include <cuda_fp16.h>
#include <math.h>
#include <stdint.h>

// Problem constants
#define RN   1024
#define CCH  384
#define NCLS 21
#define DFEAT 18816        // 384*7*7
#define HID  1024
#define BETA (1.0f/9.0f)

// GEMM tiling (single fp16 mma path)
#define BM 128
#define BN 64
#define BK 64
#define NST 3                          // pipeline stages
#define ASTRIDE 72                     // 64 elems + 8 pad -> conflict-free ldmatrix
#define A_ELEMS (BM*ASTRIDE)           // 9216
#define B_ELEMS (BN*ASTRIDE)           // 4608
#define STAGE_ELEMS (A_ELEMS + B_ELEMS)       // 13824 elems
#define GSMEM_BYTES (NST*STAGE_ELEMS*2)       // 82944 bytes
#define NSPLIT 2

// ---------------- scratch (device globals; no allocation allowed) ----------------
__device__ __align__(16) __half g_X  [RN * DFEAT];
__device__ __align__(16) __half g_W6 [HID * DFEAT];   // [N,K] transposed fp16
__device__ __align__(16) __half g_W7 [HID * HID];
__device__ __align__(16) __half g_H1 [RN * HID];
__device__ __align__(16) float g_part[NSPLIT * RN * HID];     // split-K partials
__device__ float g_H2[RN * HID];
__device__ float g_cls[RN];
__device__ float g_box[RN];

// ---------------- PTX helpers (baseline sm_80+ features only) ---------------------
__device__ __forceinline__ uint32_t smem_u32(const void* p) {
    uint32_t a;
    asm("{ .reg .u64 t; cvta.to.shared.u64 t, %1; cvt.u32.u64 %0, t; }" : "=r"(a) : "l"(p));
    return a;
}
__device__ __forceinline__ void cp16(void* sdst, const void* gsrc) {
    uint32_t d = smem_u32(sdst);
    asm volatile("cp.async.cg.shared.global [%0], [%1], 16;" :: "r"(d), "l"(gsrc) : "memory");
}
__device__ __forceinline__ void cp_commit() {
    asm volatile("cp.async.commit_group;" ::: "memory");
}
template <int N>
__device__ __forceinline__ void cp_wait() {
    asm volatile("cp.async.wait_group %0;" :: "n"(N) : "memory");
}
__device__ __forceinline__ void ldsm4(uint32_t* r, uint32_t addr) {
    asm volatile("ldmatrix.sync.aligned.m8n8.x4.shared.b16 {%0,%1,%2,%3}, [%4];"
                 : "=r"(r[0]), "=r"(r[1]), "=r"(r[2]), "=r"(r[3]) : "r"(addr));
}
__device__ __forceinline__ void mma16816(float* c, const uint32_t* a, const uint32_t* b) {
    asm volatile("mma.sync.aligned.m16n8k16.row.col.f32.f16.f16.f32 "
                 "{%0,%1,%2,%3}, {%4,%5,%6,%7}, {%8,%9}, {%0,%1,%2,%3};"
                 : "+f"(c[0]), "+f"(c[1]), "+f"(c[2]), "+f"(c[3])
                 : "r"(a[0]), "r"(a[1]), "r"(a[2]), "r"(a[3]), "r"(b[0]), "r"(b[1]));
}

// ---------------- ROIAlign: writes fp16 X -----------------------------------------
__global__ void roi_align_kernel(const float* __restrict__ p2, const float* __restrict__ p3,
                                 const float* __restrict__ p4, const float* __restrict__ p5,
                                 const float* __restrict__ rois, const int* __restrict__ batch_idx)
{
    int r = blockIdx.x;
    __shared__ float slx[14], sly[14];
    __shared__ int   sx0[14], sx1[14], sy0[14], sy1[14];
    __shared__ int   svx[14], svy[14];

    float x1 = rois[r*4+0], y1 = rois[r*4+1], x2 = rois[r*4+2], y2 = rois[r*4+3];
    float area = (x2 - x1) * (y2 - y1);
    float lf = floorf(4.0f + log2f(sqrtf(area) / 224.0f + 1e-6f));
    lf = fminf(fmaxf(lf, 2.0f), 5.0f);
    int lvl = (int)lf - 2;
    int S = 56 >> lvl;
    float scale = 0.25f / (float)(1 << lvl);
    const float* feat = (lvl == 0) ? p2 : (lvl == 1) ? p3 : (lvl == 2) ? p4 : p5;
    int b = batch_idx[r];
    const float* img0 = feat + (size_t)b * CCH * S * S;

    float x1s = x1 * scale, y1s = y1 * scale;
    float rw = fmaxf(x2 * scale - x1s, 1.0f);
    float rh = fmaxf(y2 * scale - y1s, 1.0f);

    int t = threadIdx.x;
    if (t < 14) {
        float kk = ((float)t + 0.5f) * 0.5f;
        float xs = x1s + (rw / 7.0f) * kk;
        svx[t] = (xs >= -1.0f && xs <= (float)S) ? 1 : 0;
        float x = fminf(fmaxf(xs, 0.0f), (float)(S - 1));
        float x0f = floorf(x);
        slx[t] = x - x0f;
        sx0[t] = (int)x0f;
        sx1[t] = min((int)x0f + 1, S - 1);

        float ys = y1s + (rh / 7.0f) * kk;
        svy[t] = (ys >= -1.0f && ys <= (float)S) ? 1 : 0;
        float y = fminf(fmaxf(ys, 0.0f), (float)(S - 1));
        float y0f = floorf(y);
        sly[t] = y - y0f;
        sy0[t] = (int)y0f;
        sy1[t] = min((int)y0f + 1, S - 1);
    }
    __syncthreads();

    size_t rbase = (size_t)r * DFEAT;
    for (int idx = t; idx < DFEAT; idx += blockDim.x) {
        int c  = idx / 49;
        int pp = idx - c * 49;
        int ph = pp / 7, pw = pp - ph * 7;
        const float* img = img0 + (size_t)c * S * S;
        float acc = 0.0f;
        #pragma unroll
        for (int dy = 0; dy < 2; dy++) {
            int iy = 2 * ph + dy;
            if (!svy[iy]) continue;
            float ly = sly[iy], hy = 1.0f - ly;
            int y0 = sy0[iy] * S, y1r = sy1[iy] * S;
            #pragma unroll
            for (int dx = 0; dx < 2; dx++) {
                int ix = 2 * pw + dx;
                if (!svx[ix]) continue;
                float lx = slx[ix], hx = 1.0f - lx;
                int x0 = sx0[ix], x1i = sx1[ix];
                acc += img[y0 + x0]  * (hy * hx) + img[y0 + x1i]  * (hy * lx)
                     + img[y1r + x0] * (ly * hx) + img[y1r + x1i] * (ly * lx);
            }
        }
        g_X[rbase + idx] = __float2half(acc * 0.25f);
    }
}

// ---------------- transpose to fp16: W[K,N] -> T[N,K] -----------------------------
__global__ void transpose_h(const float* __restrict__ W, __half* __restrict__ T,
                            int K, int N)
{
    __shared__ float tile[32][33];
    int k0 = blockIdx.x * 32, n0 = blockIdx.y * 32;
    int tx = threadIdx.x, ty = threadIdx.y;
    #pragma unroll
    for (int i = 0; i < 4; i++)
        tile[ty + i*8][tx] = W[(size_t)(k0 + ty + i*8) * N + n0 + tx];
    __syncthreads();
    #pragma unroll
    for (int i = 0; i < 4; i++) {
        int n = n0 + ty + i*8;
        int k = k0 + tx;
        T[(size_t)n * K + k] = __float2half(tile[tx][ty + i*8]);
    }
}

// ---------------- fp16 GEMM on mma.sync (HMMA), split-K, 3-stage -------------------
// partial[z][M,N] = A[:, z-th K slice] @ B^T; A=[M,K] fp16, B=[N,K] fp16.
__global__ __launch_bounds__(256, 2)
void gemmh(const __half* __restrict__ A, const __half* __restrict__ B,
           float* __restrict__ part, int K, int kLen)
{
    extern __shared__ __half sm[];
    int tid = threadIdx.x, wid = tid >> 5, lane = tid & 31;
    int bm = blockIdx.y * BM, bn = blockIdx.x * BN;
    int kOff = blockIdx.z * kLen;
    float* pout = part + (size_t)blockIdx.z * RN * HID;
    int wm = (wid & 3) * 32;   // warp M offset within tile
    int wn = (wid >> 2) * 32;  // warp N offset within tile

    float acc[2][4][4];
    #pragma unroll
    for (int mt = 0; mt < 2; mt++)
        #pragma unroll
        for (int nt = 0; nt < 4; nt++)
            #pragma unroll
            for (int i = 0; i < 4; i++) acc[mt][nt][i] = 0.0f;

    int nc = kLen / BK;

    // stage loader: A 128 rows x 64 (8 cp16/row) = 1024 ops; B 64 rows = 512 ops
    auto load_stage = [&](int c, int s) {
        __half* st = sm + s * STAGE_ELEMS;
        int k0 = kOff + c * BK;
        #pragma unroll
        for (int j = 0; j < 4; j++) {
            int i = tid + j * 256;
            int row = i >> 3, seg = i & 7;
            cp16(&st[row * ASTRIDE + seg * 8], &A[(size_t)(bm + row) * K + k0 + seg * 8]);
        }
        #pragma unroll
        for (int j = 0; j < 2; j++) {
            int i = tid + j * 256;
            int row = i >> 3, seg = i & 7;
            cp16(&st[A_ELEMS + row * ASTRIDE + seg * 8], &B[(size_t)(bn + row) * K + k0 + seg * 8]);
        }
        cp_commit();
    };

    // prologue: stages 0,1
    load_stage(0, 0);
    load_stage(1, 1);

    for (int c = 0; c < nc; c++) {
        if (c + 1 < nc) cp_wait<1>(); else cp_wait<0>();
        __syncthreads();          // publish stage c%NST; protect stage (c+2)%NST
        if (c + 2 < nc) load_stage(c + 2, (c + 2) % NST);

        __half* st = sm + (c % NST) * STAGE_ELEMS;
        uint32_t sA = smem_u32(st);
        #pragma unroll
        for (int ks = 0; ks < 4; ks++) {
            int kc = ks * 16;
            uint32_t ah[2][4], bb[4][2];
            #pragma unroll
            for (int mt = 0; mt < 2; mt++) {
                int row = wm + mt * 16 + (lane & 15);
                int col = kc + ((lane >> 4) << 3);
                ldsm4(ah[mt], sA + (uint32_t)(row * ASTRIDE + col) * 2);
            }
            #pragma unroll
            for (int p = 0; p < 2; p++) {
                int rown = wn + p * 16 + ((lane & 16) >> 1) + (lane & 7);
                int col = kc + (lane & 8);
                uint32_t r4[4];
                ldsm4(r4, sA + A_ELEMS * 2 + (uint32_t)(rown * ASTRIDE + col) * 2);
                bb[2*p][0] = r4[0]; bb[2*p][1] = r4[1];
                bb[2*p+1][0] = r4[2]; bb[2*p+1][1] = r4[3];
            }
            #pragma unroll
            for (int mt = 0; mt < 2; mt++)
                #pragma unroll
                for (int nt = 0; nt < 4; nt++)
                    mma16816(acc[mt][nt], ah[mt], bb[nt]);
        }
    }

    // epilogue: fp32 partial
    int lrow = lane >> 2, lcol = (lane & 3) * 2;
    #pragma unroll
    for (int mt = 0; mt < 2; mt++) {
        #pragma unroll
        for (int nt = 0; nt < 4; nt++) {
            int col = bn + wn + nt * 8 + lcol;
            #pragma unroll
            for (int half = 0; half < 2; half++) {
                int row = bm + wm + mt * 16 + lrow + half * 8;
                float2 v;
                v.x = acc[mt][nt][half * 2 + 0];
                v.y = acc[mt][nt][half * 2 + 1];
                *(float2*)&pout[(size_t)row * HID + col] = v;
            }
        }
    }
}

// ---------------- combine split-K partials + bias + relu --------------------------
// mode 1: write fp16 (Oh); mode 0: write fp32 (outf).
__global__ void combine_kernel(const float* __restrict__ part, const float* __restrict__ bias,
                               float* __restrict__ outf, __half* __restrict__ Oh, int mode)
{
    int idx = blockIdx.x * blockDim.x + threadIdx.x;   // over RN*HID
    int col = idx & (HID - 1);
    float v = part[idx] + part[RN * HID + idx] + bias[col];
    v = fmaxf(v, 0.0f);
    if (mode == 0) outf[idx] = v;
    else           Oh[idx] = __float2half(v);
}

// ---------------- head (cls logits + label-slot bbox) + per-roi losses ------------
__global__ void head_loss_kernel(const float* __restrict__ H2,
                                 const float* __restrict__ w_cls, const float* __restrict__ b_cls,
                                 const float* __restrict__ w_bbox, const float* __restrict__ b_bbox,
                                 const int* __restrict__ labels, const float* __restrict__ regt)
{
    int r = blockIdx.x;
    int t = threadIdx.x;          // 128 threads
    __shared__ float xs[HID];
    __shared__ float logits[NCLS];
    __shared__ float selv[4];

    for (int k = t; k < HID; k += 128) xs[k] = H2[(size_t)r * HID + k];
    __syncthreads();

    int label = labels[r];
    int warp = t >> 5, lane = t & 31;

    for (int j = warp; j < NCLS + 4; j += 4) {
        float s = 0.0f;
        if (j < NCLS) {
            for (int k = lane; k < HID; k += 32) s += xs[k] * w_cls[(size_t)k * NCLS + j];
        } else {
            int col = label * 4 + (j - NCLS);
            for (int k = lane; k < HID; k += 32) s += xs[k] * w_bbox[(size_t)k * (NCLS * 4) + col];
        }
        #pragma unroll
        for (int o = 16; o > 0; o >>= 1) s += __shfl_xor_sync(0xffffffffu, s, o);
        if (lane == 0) {
            if (j < NCLS) logits[j] = s + b_cls[j];
            else          selv[j - NCLS] = s + b_bbox[label * 4 + (j - NCLS)];
        }
    }
    __syncthreads();

    if (t == 0) {
        float m = -1e30f;
        #pragma unroll
        for (int j = 0; j < NCLS; j++) m = fmaxf(m, logits[j]);
        float se = 0.0f;
        #pragma unroll
        for (int j = 0; j < NCLS; j++) se += expf(logits[j] - m);
        float lse = logf(se) + m;
        float ce = lse - logits[label];
        float pt = expf(-ce);
        float fw = (1.0f - pt) * (1.0f - pt);
        float aw = (label > 0) ? 0.25f : 0.75f;
        g_cls[r] = fw * aw * ce;

        float bl = 0.0f;
        #pragma unroll
        for (int i = 0; i < 4; i++) {
            float d = selv[i] - regt[r * 4 + i];
            float ad = fabsf(d);
            bl += (ad < BETA) ? 0.5f * d * d / BETA : ad - 0.5f * BETA;
        }
        g_box[r] = (label > 0) ? bl : 0.0f;
    }
}

// ---------------- deterministic final reduction -----------------------------------
__global__ void reduce_kernel(float* __restrict__ out)
{
    __shared__ float s1[RN];
    __shared__ float s2[RN];
    int t = threadIdx.x;
    s1[t] = g_cls[t];
    s2[t] = g_box[t];
    __syncthreads();
    for (int o = RN / 2; o > 0; o >>= 1) {
        if (t < o) { s1[t] += s1[t + o]; s2[t] += s2[t + o]; }
        __syncthreads();
    }
    if (t == 0) {
        out[0] = s1[0] / (float)RN;
        out[1] = s2[0] / (float)RN;
    }
}

// ---------------- launch ----------------------------------------------------------
extern "C" void kernel_launch(void* const* d_in, const int* in_sizes, int n_in,
                              void* d_out, int out_size)
{
    const float* p2     = (const float*)d_in[0];
    const float* p3     = (const float*)d_in[1];
    const float* p4     = (const float*)d_in[2];
    const float* p5     = (const float*)d_in[3];
    const float* rois   = (const float*)d_in[4];
    const int*   bidx   = (const int*)  d_in[5];
    const int*   labels = (const int*)  d_in[6];
    const float* regt   = (const float*)d_in[7];
    const float* w_fc6  = (const float*)d_in[8];
    const float* b_fc6  = (const float*)d_in[9];
    const float* w_fc7  = (const float*)d_in[10];
    const float* b_fc7  = (const float*)d_in[11];
    const float* w_cls  = (const float*)d_in[12];
    const float* b_cls  = (const float*)d_in[13];
    const float* w_bbox = (const float*)d_in[14];
    const float* b_bbox = (const float*)d_in[15];

    __half *Xp, *W6p, *W7p, *H1p;
    float *H2p, *Pp;
    cudaGetSymbolAddress((void**)&Xp,  g_X);
    cudaGetSymbolAddress((void**)&W6p, g_W6);
    cudaGetSymbolAddress((void**)&W7p, g_W7);
    cudaGetSymbolAddress((void**)&H1p, g_H1);
    cudaGetSymbolAddress((void**)&H2p, g_H2);
    cudaGetSymbolAddress((void**)&Pp,  g_part);

    cudaFuncSetAttribute(gemmh, cudaFuncAttributeMaxDynamicSharedMemorySize, GSMEM_BYTES);

    // 1) weight transpose -> fp16 [N,K]
    transpose_h<<<dim3(DFEAT / 32, HID / 32), dim3(32, 8)>>>(w_fc6, W6p, DFEAT, HID);
    transpose_h<<<dim3(HID / 32, HID / 32),   dim3(32, 8)>>>(w_fc7, W7p, HID, HID);

    // 2) ROIAlign + flatten -> g_X fp16 [1024, 18816]
    roi_align_kernel<<<RN, 512>>>(p2, p3, p4, p5, rois, bidx);

    // 3) fc6 split-K=2: partials, then combine -> H1 fp16
    dim3 grid(HID / BN, RN / BM, NSPLIT);   // 16 x 8 x 2 = 256 CTAs
    gemmh<<<grid, 256, GSMEM_BYTES>>>(Xp, W6p, Pp, DFEAT, DFEAT / NSPLIT);
    combine_kernel<<<RN * HID / 256, 256>>>(Pp, b_fc6, nullptr, H1p, 1);

    // 4) fc7 split-K=2 -> H2 fp32
    gemmh<<<grid, 256, GSMEM_BYTES>>>(H1p, W7p, Pp, HID, HID / NSPLIT);
    combine_kernel<<<RN * HID / 256, 256>>>(Pp, b_fc7, H2p, nullptr, 0);

    // 5) heads + per-roi losses
    head_loss_kernel<<<RN, 128>>>(H2p, w_cls, b_cls, w_bbox, b_bbox, labels, regt);

    // 6) deterministic reduction -> out[0..1]
    reduce_kernel<<<1, RN>>>((float*)d_out);
}